// round 11
// baseline (speedup 1.0000x reference)
#include <cuda_runtime.h>
#include <math.h>

#define NB 8
#define NC 12
#define NNtok 785
#define NS 784
#define NH 28
#define ND 768
#define KHID 512
#define PNUM 84
#define SCL 0.7f
#define TPB 1024
#define NWB 32
#define NWA 25                        // warps covering s<784
#define NSUB 2                        // compute sub-blocks per batch
#define NCB (NB * NSUB)               // 16 compute blocks
#define NC4TOT (NB * NS * (ND / 4))   // 1,204,224 float4 (rows 1..784)
#define NCPB (148 - NCB)              // 132 copy blocks -> grid 148 = 1 wave
#define CSTRIDE (NCPB * TPB)

__device__ __forceinline__ unsigned f2key(float v) {
    unsigned b = __float_as_uint(v);
    return (b & 0x80000000u) ? ~b : (b | 0x80000000u);   // order-preserving
}
__device__ __forceinline__ void pair_bar(int id) {
    asm volatile("bar.sync %0, 64;" :: "r"(id) : "memory");
}

__global__ __launch_bounds__(TPB) void kAll(
    const float* __restrict__ x,  const float* __restrict__ w1,
    const float* __restrict__ w2, const float* __restrict__ hs,
    float* __restrict__ out, int seln)
{
    const int tid = threadIdx.x, lane = tid & 31, warp = tid >> 5;

    if (blockIdx.x >= NCB) {
        // ================= copy blocks: hs rows 1..784 -> out ==============
        const float4* hin = (const float4*)hs;
        float4* o4 = (float4*)out;
        const int cb = blockIdx.x - NCB;
        float4 v[9]; int idx[9]; bool ok[9];
        #pragma unroll
        for (int j = 0; j < 9; j++) {
            int k = cb * TPB + tid + j * CSTRIDE;
            ok[j] = (k < NC4TOT);
            if (ok[j]) {
                int b  = k / (NS * (ND / 4));
                int r  = k - b * (NS * (ND / 4));
                int n  = r / (ND / 4);
                int d4 = r - n * (ND / 4);
                idx[j] = (b * NNtok + n + 1) * (ND / 4) + d4;
                v[j]   = hin[idx[j]];
            }
        }
        #pragma unroll
        for (int j = 0; j < 9; j++) if (ok[j]) o4[idx[j]] = v[j];
        return;
    }

    // ============== compute block (b, sub): redundant per-batch stats ======
    __shared__ unsigned      msel[NC][25];      // selection bitmasks
    __shared__ int           hist[NC][256];     // per-channel radix hist
    __shared__ unsigned char whist[NWA][256];   // per-warp conv-value hist
    __shared__ unsigned char c0[NS];
    __shared__ float         msh[NS];
    __shared__ int           sfx[256];
    __shared__ short         spatch[NS];        // patch idx by rank
    __shared__ float         scoef[KHID];       // (u>0?cp:cm)*u
    __shared__ float4        gp4[8 * 96];       // GEMV k-chunk partials
    __shared__ float redf[NWB], redf2[NWB], redf3[NWB], redf4[NWB];
    __shared__ int   redi[NWB];
    __shared__ float s_mean, s_w0, s_w1, s_pa, s_cp, s_cm;
    __shared__ int   s_anchor;

    const int b = blockIdx.x >> 1, sub = blockIdx.x & 1;

    for (int i = tid; i < NWA * 256 / 4; i += TPB) ((int*)whist)[i] = 0;

    // ---- top-84 radix select: TWO warps per channel, named-barrier pair ---
    if (warp < 2 * NC) {
        const int c = warp >> 1, h = warp & 1;
        const int J0 = h ? 13 : 0, J1 = h ? 25 : 13;
        const int barid = c + 1;                 // HW named barriers 1..12
        const float* row = x + ((long long)(b * NC + c)) * NNtok * NNtok + 1;
        unsigned pref = 0u; int rem = PNUM; int binF = 0;
        #pragma unroll
        for (int pass = 0; pass < 4; pass++) {
            const int shift = 24 - 8 * pass;
            const unsigned mhi = (pass == 0) ? 0u : (0xFFFFFFFFu << (shift + 8));
            // zero my half of the 256 bins
            #pragma unroll
            for (int i = 0; i < 4; i++) hist[c][h * 128 + lane * 4 + i] = 0;
            pair_bar(barid);
            for (int j = J0; j < J1; j++) {
                int s = lane + 32 * j;
                if (s < NS) {
                    unsigned u = f2key(row[s]);          // L1-hot after pass 0
                    if ((u & mhi) == pref)
                        atomicAdd(&hist[c][(u >> shift) & 255u], 1);
                }
            }
            pair_bar(barid);
            // search (redundant in both warps of the pair, identical result)
            int hh[8], S = 0;
            #pragma unroll
            for (int i = 0; i < 8; i++) { hh[i] = hist[c][lane * 8 + i]; S += hh[i]; }
            int s = S;                                    // suffix over lanes
            #pragma unroll
            for (int o = 1; o < 32; o <<= 1) {
                int n = __shfl_down_sync(0xFFFFFFFFu, s, o);
                if (lane + o < 32) s += n;
            }
            int run = s - S;                              // sum over lanes > me
            int fbin = -1, fgt = 0;
            #pragma unroll
            for (int i = 7; i >= 0; i--) {
                int gt = run;                             // # strictly greater
                if (gt < rem && gt + hh[i] >= rem) { fbin = lane * 8 + i; fgt = gt; }
                run += hh[i];
            }
            unsigned fm = __ballot_sync(0xFFFFFFFFu, fbin >= 0);
            int src = __ffs(fm) - 1;
            binF = __shfl_sync(0xFFFFFFFFu, fbin, src);
            int gt = __shfl_sync(0xFFFFFFFFu, fgt, src);
            pref |= ((unsigned)binF) << shift;
            rem  -= gt;
            pair_bar(barid);                 // protect hist vs next-pass zero
        }
        const unsigned T = pref;            // exact 84th-largest key
        const int need  = rem;              // # of T-ties to take (asc index)
        const int cntT  = hist[c][binF];    // total # keys == T (still valid)
        const bool fast = (cntT == need);   // all ties taken -> sel = (u>=T)
        int cum = 0;
        if (!fast && h == 1) {              // rare: count T-ties in half 0
            for (int j = 0; j < 13; j++) {
                unsigned u = f2key(row[lane + 32 * j]);
                cum += __popc(__ballot_sync(0xFFFFFFFFu, u == T));
            }
        }
        for (int j = J0; j < J1; j++) {
            int s = lane + 32 * j;
            bool valid = (s < NS);
            unsigned u = valid ? f2key(row[s]) : (T ^ 1u);
            bool sel;
            if (fast) {
                sel = valid && (u >= T);
            } else {
                unsigned eqm = __ballot_sync(0xFFFFFFFFu, valid && (u == T));
                sel = valid && (u > T ||
                      (u == T && (cum + __popc(eqm & ((1u << lane) - 1u)) < need)));
                cum += __popc(eqm);
            }
            unsigned smask = __ballot_sync(0xFFFFFFFFu, sel);
            if (lane == 0) msel[c][j] = smask;
        }
    }
    __syncthreads();

    // ---- m[s] = sum_c (sel ? v : 0.7v);  c0[s] = sum_c sel ---------------
    const bool act = (tid < NS);
    float m = 0.f;
    if (act) {
        const long long xb = (long long)b * NC * NNtok * NNtok;
        const int jw = tid >> 5; const unsigned bit = 1u << (tid & 31);
        int cnt = 0;
        #pragma unroll
        for (int c = 0; c < NC; c++) {
            float v = x[xb + (long long)c * NNtok * NNtok + 1 + tid];  // L1-hot
            bool sel = (msel[c][jw] & bit) != 0u;
            m += sel ? v : v * SCL;
            cnt += sel ? 1 : 0;
        }
        msh[tid] = m;
        c0[tid]  = (unsigned char)cnt;
    }

    // ---- pass 1: mean + c+ + c-  (all independent of anchor) -------------
    {
        float p  = act ? m * (1.0f / NC) : 0.f;
        float ps = act ? m : 0.f;
        float cpv = (p > 0.f) ? p * p : 0.f;
        float cmv = (p < 0.f) ? p * p : 0.f;
        for (int o = 16; o; o >>= 1) {
            ps  += __shfl_xor_sync(0xFFFFFFFFu, ps,  o);
            cpv += __shfl_xor_sync(0xFFFFFFFFu, cpv, o);
            cmv += __shfl_xor_sync(0xFFFFFFFFu, cmv, o);
        }
        if (lane == 0) { redf[warp] = ps; redf2[warp] = cpv; redf3[warp] = cmv; }
        __syncthreads();
        if (warp == 0) {
            float a = redf[lane], c = redf2[lane], d = redf3[lane];
            for (int o = 16; o; o >>= 1) {
                a += __shfl_xor_sync(0xFFFFFFFFu, a, o);
                c += __shfl_xor_sync(0xFFFFFFFFu, c, o);
                d += __shfl_xor_sync(0xFFFFFFFFu, d, o);
            }
            if (lane == 0) { s_mean = a / (float)NS; s_cp = c; s_cm = d; }
        }
        __syncthreads();
    }

    // ---- pass 2: anchor = argmax(binary*m/C), first-index tie-break ------
    {
        float bv = -1e30f; int bi = NS;
        if (act) { float v = (m > s_mean) ? m * (1.0f / NC) : 0.0f; bv = v; bi = tid; }
        for (int o = 16; o; o >>= 1) {
            float ov = __shfl_xor_sync(0xFFFFFFFFu, bv, o);
            int   oi = __shfl_xor_sync(0xFFFFFFFFu, bi, o);
            if (ov > bv || (ov == bv && oi < bi)) { bv = ov; bi = oi; }
        }
        if (lane == 0) { redf[warp] = bv; redi[warp] = bi; }
        __syncthreads();
        if (warp == 0) {
            float v = redf[lane]; int i = redi[lane];
            for (int o = 16; o; o >>= 1) {
                float ov = __shfl_xor_sync(0xFFFFFFFFu, v, o);
                int   oi = __shfl_xor_sync(0xFFFFFFFFu, i, o);
                if (ov > v || (ov == v && oi < i)) { v = ov; i = oi; }
            }
            if (lane == 0) { s_anchor = i; s_pa = msh[i] * (1.0f / NC); }
        }
        __syncthreads();
    }
    const int anchor = s_anchor;
    const float ai = (float)(anchor / NH), aj = (float)(anchor % NH);

    // ---- pass 3: w0 = sum pw*dist, w1 = sum pw*ang -----------------------
    {
        float w0 = 0.f, w1s = 0.f;
        if (act) {
            float p   = m * (1.0f / NC);
            float rc0 = ((float)(tid / NH) - ai) / (float)NH;
            float rc1 = ((float)(tid % NH) - aj) / (float)NH;
            w0  = p * sqrtf(rc0 * rc0 + rc1 * rc1);
            w1s = p * (atan2f(rc1, rc0) * 0.3183098861837907f + 1.0f) * 0.5f;
        }
        for (int o = 16; o; o >>= 1) {
            w0  += __shfl_xor_sync(0xFFFFFFFFu, w0,  o);
            w1s += __shfl_xor_sync(0xFFFFFFFFu, w1s, o);
        }
        if (lane == 0) { redf[warp] = w0; redf4[warp] = w1s; }
        __syncthreads();
        if (warp == 0) {
            float a = redf[lane], bb = redf4[lane];
            for (int o = 16; o; o >>= 1) {
                a  += __shfl_xor_sync(0xFFFFFFFFu, a,  o);
                bb += __shfl_xor_sync(0xFFFFFFFFu, bb, o);
            }
            if (lane == 0) { s_w0 = a; s_w1 = bb; }
        }
        __syncthreads();
    }

    // ---- coef[k] = (u>0 ? cp : cm) * u  (cp*u+ - cm*u- collapses) --------
    if (tid < KHID) {
        float u = s_w0 * w1[tid] + s_w1 * w1[KHID + tid];
        scoef[tid] = u * (u > 0.f ? s_cp : s_cm);
    }

    // ---- 3x3 conv + per-warp value histogram -----------------------------
    int vcc = 0; unsigned mm;
    if (act) {
        int i0 = tid / NH, j0 = tid % NH;
        #pragma unroll
        for (int di = -1; di <= 1; di++)
            #pragma unroll
            for (int dj = -1; dj <= 1; dj++) {
                int ii = i0 + di, jj = j0 + dj;
                if (ii >= 0 && ii < NH && jj >= 0 && jj < NH)
                    vcc += (2 - abs(di)) * (2 - abs(dj)) * (int)c0[ii * NH + jj];
            }
    }
    {
        int key = act ? vcc : 999;
        mm = __match_any_sync(0xFFFFFFFFu, key);
        if (act && lane == (__ffs(mm) - 1))
            whist[warp][vcc] = (unsigned char)__popc(mm);
    }
    __syncthreads();

    // ---- sfx[v] = # strictly greater (suffix over 256 bins) --------------
    int sh = 0, ss = 0;
    if (tid < 256) {
        #pragma unroll
        for (int r = 0; r < NWA; r++) sh += (int)whist[r][tid];
        ss = sh;
        #pragma unroll
        for (int o = 1; o < 32; o <<= 1) {
            int n = __shfl_up_sync(0xFFFFFFFFu, ss, o);
            if (lane >= o) ss += n;
        }
        if (lane == 31) redi[tid >> 5] = ss;
    }
    __syncthreads();
    if (tid < 256) {
        int off = 0, total = 0;
        #pragma unroll
        for (int r = 0; r < 8; r++) {
            int w = redi[r]; total += w; if (r < (tid >> 5)) off += w;
        }
        sfx[tid] = total - (ss + off);
    }
    __syncthreads();

    // ---- stable descending ranks -> smem patch list ----------------------
    if (act) {
        int g = sfx[vcc];
        if (g < seln) {
            int e = __popc(mm & ((1u << lane) - 1u));
            for (int r = 0; r < warp; r++) e += (int)whist[r][vcc];
            int rk = g + e;                 // ties by ascending index (stable)
            if (rk < seln) spatch[rk] = (short)(tid + 1);
        }
    }

    // ---- GEMV split by sub: 96 col-groups x 8 k-chunks of 64 -------------
    if (tid < 768) {
        const int g  = tid % 96;            // 4 cols/group: cols sub*384+4g..
        const int ks = tid / 96;            // 0..7
        const float4* w4 = (const float4*)w2 + sub * 96 + g;
        float4 acc = make_float4(0.f, 0.f, 0.f, 0.f);
        #pragma unroll 8
        for (int k = ks * 64; k < ks * 64 + 64; k++) {
            float c = scoef[k];
            float4 w = __ldg(w4 + (size_t)k * (ND / 4));
            acc.x += c * w.x; acc.y += c * w.y; acc.z += c * w.z; acc.w += c * w.w;
        }
        gp4[tid] = acc;
    }
    __syncthreads();
    if (tid < 96) {
        float4 v = make_float4(0.f, 0.f, 0.f, 0.f);
        #pragma unroll
        for (int r = 0; r < 8; r++) {
            float4 a = gp4[r * 96 + tid];
            v.x += a.x; v.y += a.y; v.z += a.z; v.w += a.w;
        }
        v.x *= s_pa; v.y *= s_pa; v.z *= s_pa; v.w *= s_pa;
        v.x = v.x > 0.f ? v.x : 0.2f * v.x;
        v.y = v.y > 0.f ? v.y : 0.2f * v.y;
        v.z = v.z > 0.f ? v.z : 0.2f * v.z;
        v.w = v.w > 0.f ? v.w : 0.2f * v.w;
        const int fi4 = b * NNtok * (ND / 4) + sub * 96 + tid;   // row 0
        float4 h4 = ((const float4*)hs)[fi4];
        v.x += h4.x; v.y += h4.y; v.z += h4.z; v.w += h4.w;
        ((float4*)out)[fi4] = v;
    }

    // ---- gather: this sub-block handles rows q = sub, sub+2, ... ---------
    {
        const float4* hin = (const float4*)hs;
        float4* o4 = (float4*)out;
        const int nh = (seln - sub + 1) / 2;               // # rows we own
        const int tot = nh * (ND / 4);
        for (int t = tid; t < tot; t += TPB) {
            int r  = t / (ND / 4);
            int d4 = t - r * (ND / 4);
            int q  = 2 * r + sub;
            int p  = (int)spatch[q];       // in [1,784]: unmodified hs rows
            o4[NB * NNtok * (ND / 4) + (b * seln + q) * (ND / 4) + d4] =
                hin[(b * NNtok + p) * (ND / 4) + d4];
        }
    }
}

// ---------------- launch ----------------
extern "C" void kernel_launch(void* const* d_in, const int* in_sizes, int n_in,
                              void* d_out, int out_size)
{
    const float* hs = (const float*)d_in[0];
    const float* x  = (const float*)d_in[1];
    const float* w1 = (const float*)d_in[2];
    const float* w2 = (const float*)d_in[3];

    const int hs_elems = NB * NNtok * ND;
    int seln = (out_size - hs_elems) / (NB * ND);
    if (seln < 1) seln = 1;
    if (seln > NS) seln = NS;

    kAll<<<NCB + NCPB, TPB>>>(x, w1, w2, hs, (float*)d_out, seln);
}

// round 12
// speedup vs baseline: 1.2549x; 1.2549x over previous
#include <cuda_runtime.h>
#include <math.h>

#define NB 8
#define NC 12
#define NNtok 785
#define NS 784
#define NH 28
#define ND 768
#define KHID 512
#define PNUM 84
#define SCL 0.7f
#define TPB 1024
#define NWB 32
#define NWA 25                        // warps covering s<784
#define NSUB 2                        // compute sub-blocks per batch
#define NCB (NB * NSUB)               // 16 compute blocks
#define NC4TOT (NB * NS * (ND / 4))   // 1,204,224 float4 (rows 1..784)
#define NCPB (148 - NCB)              // 132 copy blocks -> grid 148 = 1 wave
#define CSTRIDE (NCPB * TPB)

__device__ __forceinline__ unsigned f2key(float v) {
    unsigned b = __float_as_uint(v);
    return (b & 0x80000000u) ? ~b : (b | 0x80000000u);   // order-preserving
}

__global__ __launch_bounds__(TPB) void kAll(
    const float* __restrict__ x,  const float* __restrict__ w1,
    const float* __restrict__ w2, const float* __restrict__ hs,
    float* __restrict__ out, int seln)
{
    const int tid = threadIdx.x, lane = tid & 31, warp = tid >> 5;

    if (blockIdx.x >= NCB) {
        // ================= copy blocks: hs rows 1..784 -> out ==============
        const float4* hin = (const float4*)hs;
        float4* o4 = (float4*)out;
        const int cb = blockIdx.x - NCB;
        float4 v[9]; int idx[9]; bool ok[9];
        #pragma unroll
        for (int j = 0; j < 9; j++) {
            int k = cb * TPB + tid + j * CSTRIDE;
            ok[j] = (k < NC4TOT);
            if (ok[j]) {
                int b  = k / (NS * (ND / 4));
                int r  = k - b * (NS * (ND / 4));
                int n  = r / (ND / 4);
                int d4 = r - n * (ND / 4);
                idx[j] = (b * NNtok + n + 1) * (ND / 4) + d4;
                v[j]   = hin[idx[j]];
            }
        }
        #pragma unroll
        for (int j = 0; j < 9; j++) if (ok[j]) o4[idx[j]] = v[j];
        return;
    }

    // ============== compute block (b, sub): redundant per-batch stats ======
    __shared__ unsigned      msel[NC][25];      // selection bitmasks
    __shared__ int           hist[NC][256];     // per-channel radix hist
    __shared__ unsigned char whist[NWA][256];   // per-warp conv-value hist
    __shared__ unsigned char c0[NS];
    __shared__ float         msh[NS];
    __shared__ int           sfx[256];
    __shared__ short         spatch[NS];        // patch idx by rank
    __shared__ float         scoef[KHID];       // (u>0?cp:cm)*u
    __shared__ float4        gp4[8 * 96];       // GEMV k-chunk partials
    __shared__ float redf[NWB], redf2[NWB], redf3[NWB], redf4[NWB];
    __shared__ int   redi[NWB];
    __shared__ float s_mean, s_w0, s_w1, s_pa, s_cp, s_cm;
    __shared__ int   s_anchor;

    const int b = blockIdx.x >> 1, sub = blockIdx.x & 1;

    for (int i = tid; i < NWA * 256 / 4; i += TPB) ((int*)whist)[i] = 0;

    // ---- warp-local top-84 radix select, one channel per warp (0..11) ----
    // Keys register-resident across all passes (25 per lane, fully unrolled).
    if (warp < NC) {
        const int c = warp;
        const float* row = x + ((long long)(b * NC + c)) * NNtok * NNtok + 1;
        unsigned ukey[25];
        #pragma unroll
        for (int j = 0; j < 25; j++) {
            int s = lane + 32 * j;
            ukey[j] = (s < NS) ? f2key(row[s]) : 0u;   // 0 = smallest key
        }
        unsigned pref = 0u; int rem = PNUM; int binF = 0;
        #pragma unroll
        for (int pass = 0; pass < 4; pass++) {
            const int shift = 24 - 8 * pass;
            const unsigned mhi = (pass == 0) ? 0u : (0xFFFFFFFFu << (shift + 8));
            #pragma unroll
            for (int i = 0; i < 8; i++) hist[c][lane * 8 + i] = 0;
            __syncwarp();
            #pragma unroll
            for (int j = 0; j < 25; j++) {
                unsigned u = ukey[j];
                if ((lane + 32 * j < NS) && (u & mhi) == pref)
                    atomicAdd(&hist[c][(u >> shift) & 255u], 1);
            }
            __syncwarp();
            int hh[8], S = 0;
            #pragma unroll
            for (int i = 0; i < 8; i++) { hh[i] = hist[c][lane * 8 + i]; S += hh[i]; }
            int s = S;                                 // suffix over lanes
            #pragma unroll
            for (int o = 1; o < 32; o <<= 1) {
                int n = __shfl_down_sync(0xFFFFFFFFu, s, o);
                if (lane + o < 32) s += n;
            }
            int run = s - S;                           // sum over lanes > me
            int fbin = -1, fgt = 0;
            #pragma unroll
            for (int i = 7; i >= 0; i--) {
                int gt = run;                          // # keys strictly greater
                if (gt < rem && gt + hh[i] >= rem) { fbin = lane * 8 + i; fgt = gt; }
                run += hh[i];
            }
            unsigned fm = __ballot_sync(0xFFFFFFFFu, fbin >= 0);
            int src = __ffs(fm) - 1;
            binF = __shfl_sync(0xFFFFFFFFu, fbin, src);
            int gt = __shfl_sync(0xFFFFFFFFu, fgt, src);
            pref |= ((unsigned)binF) << shift;
            rem  -= gt;
            __syncwarp();
        }
        const unsigned T = pref;            // exact 84th-largest key
        const int need  = rem;              // # of T-ties to take (asc index)
        const int cntT  = hist[c][binF];    // total # keys == T
        if (cntT == need) {
            // fast path (virtually always for continuous keys): take all ties
            #pragma unroll
            for (int j = 0; j < 25; j++) {
                bool sel = (lane + 32 * j < NS) && (ukey[j] >= T);
                unsigned smask = __ballot_sync(0xFFFFFFFFu, sel);
                if (lane == 0) msel[c][j] = smask;
            }
        } else {
            int cum = 0;
            #pragma unroll
            for (int j = 0; j < 25; j++) {
                bool valid = (lane + 32 * j < NS);
                unsigned u = valid ? ukey[j] : (T ^ 1u);
                unsigned eqm = __ballot_sync(0xFFFFFFFFu, valid && (u == T));
                bool sel = valid && (u > T ||
                          (u == T && (cum + __popc(eqm & ((1u << lane) - 1u)) < need)));
                unsigned smask = __ballot_sync(0xFFFFFFFFu, sel);
                if (lane == 0) msel[c][j] = smask;
                cum += __popc(eqm);
            }
        }
    }
    __syncthreads();

    // ---- m[s] = sum_c (sel ? v : 0.7v);  c0[s] = sum_c sel ---------------
    const bool act = (tid < NS);
    float m = 0.f;
    if (act) {
        const long long xb = (long long)b * NC * NNtok * NNtok;
        const int jw = tid >> 5; const unsigned bit = 1u << (tid & 31);
        int cnt = 0;
        #pragma unroll
        for (int c = 0; c < NC; c++) {
            float v = x[xb + (long long)c * NNtok * NNtok + 1 + tid];  // L1-hot
            bool sel = (msel[c][jw] & bit) != 0u;
            m += sel ? v : v * SCL;
            cnt += sel ? 1 : 0;
        }
        msh[tid] = m;
        c0[tid]  = (unsigned char)cnt;
    }

    // ---- pass 1: mean + c+ + c-  (all independent of anchor) -------------
    {
        float p  = act ? m * (1.0f / NC) : 0.f;
        float ps = act ? m : 0.f;
        float cpv = (p > 0.f) ? p * p : 0.f;
        float cmv = (p < 0.f) ? p * p : 0.f;
        for (int o = 16; o; o >>= 1) {
            ps  += __shfl_xor_sync(0xFFFFFFFFu, ps,  o);
            cpv += __shfl_xor_sync(0xFFFFFFFFu, cpv, o);
            cmv += __shfl_xor_sync(0xFFFFFFFFu, cmv, o);
        }
        if (lane == 0) { redf[warp] = ps; redf2[warp] = cpv; redf3[warp] = cmv; }
        __syncthreads();
        if (warp == 0) {
            float a = redf[lane], c = redf2[lane], d = redf3[lane];
            for (int o = 16; o; o >>= 1) {
                a += __shfl_xor_sync(0xFFFFFFFFu, a, o);
                c += __shfl_xor_sync(0xFFFFFFFFu, c, o);
                d += __shfl_xor_sync(0xFFFFFFFFu, d, o);
            }
            if (lane == 0) { s_mean = a / (float)NS; s_cp = c; s_cm = d; }
        }
        __syncthreads();
    }

    // ---- pass 2: anchor = argmax(binary*m/C), first-index tie-break ------
    {
        float bv = -1e30f; int bi = NS;
        if (act) { float v = (m > s_mean) ? m * (1.0f / NC) : 0.0f; bv = v; bi = tid; }
        for (int o = 16; o; o >>= 1) {
            float ov = __shfl_xor_sync(0xFFFFFFFFu, bv, o);
            int   oi = __shfl_xor_sync(0xFFFFFFFFu, bi, o);
            if (ov > bv || (ov == bv && oi < bi)) { bv = ov; bi = oi; }
        }
        if (lane == 0) { redf[warp] = bv; redi[warp] = bi; }
        __syncthreads();
        if (warp == 0) {
            float v = redf[lane]; int i = redi[lane];
            for (int o = 16; o; o >>= 1) {
                float ov = __shfl_xor_sync(0xFFFFFFFFu, v, o);
                int   oi = __shfl_xor_sync(0xFFFFFFFFu, i, o);
                if (ov > v || (ov == v && oi < i)) { v = ov; i = oi; }
            }
            if (lane == 0) { s_anchor = i; s_pa = msh[i] * (1.0f / NC); }
        }
        __syncthreads();
    }
    const int anchor = s_anchor;
    const float ai = (float)(anchor / NH), aj = (float)(anchor % NH);

    // ---- pass 3: w0 = sum pw*dist, w1 = sum pw*ang -----------------------
    {
        float w0 = 0.f, w1s = 0.f;
        if (act) {
            float p   = m * (1.0f / NC);
            float rc0 = ((float)(tid / NH) - ai) / (float)NH;
            float rc1 = ((float)(tid % NH) - aj) / (float)NH;
            w0  = p * sqrtf(rc0 * rc0 + rc1 * rc1);
            w1s = p * (atan2f(rc1, rc0) * 0.3183098861837907f + 1.0f) * 0.5f;
        }
        for (int o = 16; o; o >>= 1) {
            w0  += __shfl_xor_sync(0xFFFFFFFFu, w0,  o);
            w1s += __shfl_xor_sync(0xFFFFFFFFu, w1s, o);
        }
        if (lane == 0) { redf[warp] = w0; redf4[warp] = w1s; }
        __syncthreads();
        if (warp == 0) {
            float a = redf[lane], bb = redf4[lane];
            for (int o = 16; o; o >>= 1) {
                a  += __shfl_xor_sync(0xFFFFFFFFu, a,  o);
                bb += __shfl_xor_sync(0xFFFFFFFFu, bb, o);
            }
            if (lane == 0) { s_w0 = a; s_w1 = bb; }
        }
        __syncthreads();
    }

    // ---- coef[k] = (u>0 ? cp : cm) * u  (cp*u+ - cm*u- collapses) --------
    if (tid < KHID) {
        float u = s_w0 * w1[tid] + s_w1 * w1[KHID + tid];
        scoef[tid] = u * (u > 0.f ? s_cp : s_cm);
    }

    // ---- 3x3 conv + per-warp value histogram -----------------------------
    int vcc = 0; unsigned mm;
    if (act) {
        int i0 = tid / NH, j0 = tid % NH;
        #pragma unroll
        for (int di = -1; di <= 1; di++)
            #pragma unroll
            for (int dj = -1; dj <= 1; dj++) {
                int ii = i0 + di, jj = j0 + dj;
                if (ii >= 0 && ii < NH && jj >= 0 && jj < NH)
                    vcc += (2 - abs(di)) * (2 - abs(dj)) * (int)c0[ii * NH + jj];
            }
    }
    {
        int key = act ? vcc : 999;
        mm = __match_any_sync(0xFFFFFFFFu, key);
        if (act && lane == (__ffs(mm) - 1))
            whist[warp][vcc] = (unsigned char)__popc(mm);
    }
    __syncthreads();

    // ---- sfx[v] = # strictly greater (suffix over 256 bins) --------------
    int sh = 0, ss = 0;
    if (tid < 256) {
        #pragma unroll
        for (int r = 0; r < NWA; r++) sh += (int)whist[r][tid];
        ss = sh;
        #pragma unroll
        for (int o = 1; o < 32; o <<= 1) {
            int n = __shfl_up_sync(0xFFFFFFFFu, ss, o);
            if (lane >= o) ss += n;
        }
        if (lane == 31) redi[tid >> 5] = ss;
    }
    __syncthreads();
    if (tid < 256) {
        int off = 0, total = 0;
        #pragma unroll
        for (int r = 0; r < 8; r++) {
            int w = redi[r]; total += w; if (r < (tid >> 5)) off += w;
        }
        sfx[tid] = total - (ss + off);
    }
    __syncthreads();

    // ---- stable descending ranks -> smem patch list ----------------------
    if (act) {
        int g = sfx[vcc];
        if (g < seln) {
            int e = __popc(mm & ((1u << lane) - 1u));
            for (int r = 0; r < warp; r++) e += (int)whist[r][vcc];
            int rk = g + e;                 // ties by ascending index (stable)
            if (rk < seln) spatch[rk] = (short)(tid + 1);
        }
    }

    // ---- GEMV split by sub: 96 col-groups x 8 k-chunks of 64 -------------
    if (tid < 768) {
        const int g  = tid % 96;            // 4 cols/group: cols sub*384+4g..
        const int ks = tid / 96;            // 0..7
        const float4* w4 = (const float4*)w2 + sub * 96 + g;
        float4 acc = make_float4(0.f, 0.f, 0.f, 0.f);
        #pragma unroll 8
        for (int k = ks * 64; k < ks * 64 + 64; k++) {
            float c = scoef[k];
            float4 w = __ldg(w4 + (size_t)k * (ND / 4));
            acc.x += c * w.x; acc.y += c * w.y; acc.z += c * w.z; acc.w += c * w.w;
        }
        gp4[tid] = acc;
    }
    __syncthreads();
    if (tid < 96) {
        float4 v = make_float4(0.f, 0.f, 0.f, 0.f);
        #pragma unroll
        for (int r = 0; r < 8; r++) {
            float4 a = gp4[r * 96 + tid];
            v.x += a.x; v.y += a.y; v.z += a.z; v.w += a.w;
        }
        v.x *= s_pa; v.y *= s_pa; v.z *= s_pa; v.w *= s_pa;
        v.x = v.x > 0.f ? v.x : 0.2f * v.x;
        v.y = v.y > 0.f ? v.y : 0.2f * v.y;
        v.z = v.z > 0.f ? v.z : 0.2f * v.z;
        v.w = v.w > 0.f ? v.w : 0.2f * v.w;
        const int fi4 = b * NNtok * (ND / 4) + sub * 96 + tid;   // row 0
        float4 h4 = ((const float4*)hs)[fi4];
        v.x += h4.x; v.y += h4.y; v.z += h4.z; v.w += h4.w;
        ((float4*)out)[fi4] = v;
    }

    // ---- gather: this sub-block handles rows q = sub, sub+2, ... ---------
    {
        const float4* hin = (const float4*)hs;
        float4* o4 = (float4*)out;
        const int nh = (seln - sub + 1) / 2;               // # rows we own
        const int tot = nh * (ND / 4);
        for (int t = tid; t < tot; t += TPB) {
            int r  = t / (ND / 4);
            int d4 = t - r * (ND / 4);
            int q  = 2 * r + sub;
            int p  = (int)spatch[q];       // in [1,784]: unmodified hs rows
            o4[NB * NNtok * (ND / 4) + (b * seln + q) * (ND / 4) + d4] =
                hin[(b * NNtok + p) * (ND / 4) + d4];
        }
    }
}

// ---------------- launch ----------------
extern "C" void kernel_launch(void* const* d_in, const int* in_sizes, int n_in,
                              void* d_out, int out_size)
{
    const float* hs = (const float*)d_in[0];
    const float* x  = (const float*)d_in[1];
    const float* w1 = (const float*)d_in[2];
    const float* w2 = (const float*)d_in[3];

    const int hs_elems = NB * NNtok * ND;
    int seln = (out_size - hs_elems) / (NB * ND);
    if (seln < 1) seln = 1;
    if (seln > NS) seln = NS;

    kAll<<<NCB + NCPB, TPB>>>(x, w1, w2, hs, (float*)d_out, seln);
}

// round 13
// speedup vs baseline: 1.4444x; 1.1510x over previous
#include <cuda_runtime.h>
#include <math.h>

#define NB 8
#define NC 12
#define NNtok 785
#define NS 784
#define NH 28
#define ND 768
#define KHID 512
#define PNUM 84
#define SCL 0.7f
#define TPB 1024
#define NWB 32
#define NWA 25                        // warps covering s<784
#define NSUB 4                        // compute sub-blocks per batch
#define NCB (NB * NSUB)               // 32 compute blocks
#define NC4TOT (NB * NS * (ND / 4))   // 1,204,224 float4 (rows 1..784)
#define NCPB (148 - NCB)              // 116 copy blocks -> grid 148 = 1 wave
#define CSTRIDE (NCPB * TPB)
#define CPR 11                        // copy rounds: 11*118784 >= NC4TOT

__device__ __forceinline__ unsigned f2key(float v) {
    unsigned b = __float_as_uint(v);
    return (b & 0x80000000u) ? ~b : (b | 0x80000000u);   // order-preserving
}

__global__ __launch_bounds__(TPB) void kAll(
    const float* __restrict__ x,  const float* __restrict__ w1,
    const float* __restrict__ w2, const float* __restrict__ hs,
    float* __restrict__ out, int seln)
{
    const int tid = threadIdx.x, lane = tid & 31, warp = tid >> 5;

    if (blockIdx.x >= NCB) {
        // ================= copy blocks: hs rows 1..784 -> out ==============
        const float4* hin = (const float4*)hs;
        float4* o4 = (float4*)out;
        const int cb = blockIdx.x - NCB;
        float4 v[CPR]; int idx[CPR]; bool ok[CPR];
        #pragma unroll
        for (int j = 0; j < CPR; j++) {
            int k = cb * TPB + tid + j * CSTRIDE;
            ok[j] = (k < NC4TOT);
            if (ok[j]) {
                int b  = k / (NS * (ND / 4));
                int r  = k - b * (NS * (ND / 4));
                int n  = r / (ND / 4);
                int d4 = r - n * (ND / 4);
                idx[j] = (b * NNtok + n + 1) * (ND / 4) + d4;
                v[j]   = hin[idx[j]];
            }
        }
        #pragma unroll
        for (int j = 0; j < CPR; j++) if (ok[j]) o4[idx[j]] = v[j];
        return;
    }

    // ============== compute block (b, sub): redundant per-batch stats ======
    __shared__ unsigned      msel[NC][25];      // selection bitmasks
    __shared__ int           hist[NC][256];     // per-channel radix hist
    __shared__ unsigned char whist[NWA][256];   // per-warp conv-value hist
    __shared__ unsigned char c0[NS];
    __shared__ float         msh[NS];
    __shared__ int           sfx[256];
    __shared__ short         spatch[NS];        // patch idx by rank
    __shared__ float         scoef[KHID];       // (u>0?cp:cm)*u
    __shared__ float4        gp4[16 * 48];      // GEMV k-chunk partials
    __shared__ float redf[NWB], redf2[NWB], redf3[NWB], redf4[NWB];
    __shared__ int   redi[NWB];
    __shared__ float s_mean, s_w0, s_w1, s_pa, s_cp, s_cm, s_maxm;
    __shared__ int   s_anchor;

    const int b = blockIdx.x >> 2, sub = blockIdx.x & 3;

    for (int i = tid; i < NWA * 256 / 4; i += TPB) ((int*)whist)[i] = 0;

    // ---- warp-local top-84 radix select, one channel per warp (0..11) ----
    if (warp < NC) {
        const int c = warp;
        const float* row = x + ((long long)(b * NC + c)) * NNtok * NNtok + 1;
        unsigned ukey[25];
        #pragma unroll
        for (int j = 0; j < 25; j++) {
            int s = lane + 32 * j;
            ukey[j] = (s < NS) ? f2key(row[s]) : 0u;   // 0 = smallest key
        }
        unsigned pref = 0u; int rem = PNUM; int binF = 0;
        #pragma unroll
        for (int pass = 0; pass < 4; pass++) {
            const int shift = 24 - 8 * pass;
            const unsigned mhi = (pass == 0) ? 0u : (0xFFFFFFFFu << (shift + 8));
            #pragma unroll
            for (int i = 0; i < 8; i++) hist[c][lane * 8 + i] = 0;
            __syncwarp();
            #pragma unroll
            for (int j = 0; j < 25; j++) {
                unsigned u = ukey[j];
                if ((lane + 32 * j < NS) && (u & mhi) == pref)
                    atomicAdd(&hist[c][(u >> shift) & 255u], 1);
            }
            __syncwarp();
            int hh[8], S = 0;
            #pragma unroll
            for (int i = 0; i < 8; i++) { hh[i] = hist[c][lane * 8 + i]; S += hh[i]; }
            int s = S;                                 // suffix over lanes
            #pragma unroll
            for (int o = 1; o < 32; o <<= 1) {
                int n = __shfl_down_sync(0xFFFFFFFFu, s, o);
                if (lane + o < 32) s += n;
            }
            int run = s - S;                           // sum over lanes > me
            int fbin = -1, fgt = 0;
            #pragma unroll
            for (int i = 7; i >= 0; i--) {
                int gt = run;                          // # keys strictly greater
                if (gt < rem && gt + hh[i] >= rem) { fbin = lane * 8 + i; fgt = gt; }
                run += hh[i];
            }
            unsigned fm = __ballot_sync(0xFFFFFFFFu, fbin >= 0);
            int src = __ffs(fm) - 1;
            binF = __shfl_sync(0xFFFFFFFFu, fbin, src);
            int gt = __shfl_sync(0xFFFFFFFFu, fgt, src);
            pref |= ((unsigned)binF) << shift;
            rem  -= gt;
            __syncwarp();
        }
        const unsigned T = pref;            // exact 84th-largest key
        const int need  = rem;              // # of T-ties to take (asc index)
        const int cntT  = hist[c][binF];    // total # keys == T
        if (cntT == need) {
            #pragma unroll
            for (int j = 0; j < 25; j++) {
                bool sel = (lane + 32 * j < NS) && (ukey[j] >= T);
                unsigned smask = __ballot_sync(0xFFFFFFFFu, sel);
                if (lane == 0) msel[c][j] = smask;
            }
        } else {
            int cum = 0;
            #pragma unroll
            for (int j = 0; j < 25; j++) {
                bool valid = (lane + 32 * j < NS);
                unsigned u = valid ? ukey[j] : (T ^ 1u);
                unsigned eqm = __ballot_sync(0xFFFFFFFFu, valid && (u == T));
                bool sel = valid && (u > T ||
                          (u == T && (cum + __popc(eqm & ((1u << lane) - 1u)) < need)));
                unsigned smask = __ballot_sync(0xFFFFFFFFu, sel);
                if (lane == 0) msel[c][j] = smask;
                cum += __popc(eqm);
            }
        }
    }
    __syncthreads();

    // ---- m[s] = sum_c (sel ? v : 0.7v);  c0[s] = sum_c sel ---------------
    const bool act = (tid < NS);
    float m = 0.f;
    if (act) {
        const long long xb = (long long)b * NC * NNtok * NNtok;
        const int jw = tid >> 5; const unsigned bit = 1u << (tid & 31);
        int cnt = 0;
        #pragma unroll
        for (int c = 0; c < NC; c++) {
            float v = x[xb + (long long)c * NNtok * NNtok + 1 + tid];  // L1-hot
            bool sel = (msel[c][jw] & bit) != 0u;
            m += sel ? v : v * SCL;
            cnt += sel ? 1 : 0;
        }
        msh[tid] = m;
        c0[tid]  = (unsigned char)cnt;
    }

    // ---- pass 1: mean + c+ + c- + (max m, argmax) simultaneously ---------
    {
        float p  = act ? m * (1.0f / NC) : 0.f;
        float ps = act ? m : 0.f;
        float cpv = (p > 0.f) ? p * p : 0.f;
        float cmv = (p < 0.f) ? p * p : 0.f;
        float bv = act ? m : -1e30f; int bi = act ? tid : NS;
        for (int o = 16; o; o >>= 1) {
            ps  += __shfl_xor_sync(0xFFFFFFFFu, ps,  o);
            cpv += __shfl_xor_sync(0xFFFFFFFFu, cpv, o);
            cmv += __shfl_xor_sync(0xFFFFFFFFu, cmv, o);
            float ov = __shfl_xor_sync(0xFFFFFFFFu, bv, o);
            int   oi = __shfl_xor_sync(0xFFFFFFFFu, bi, o);
            if (ov > bv || (ov == bv && oi < bi)) { bv = ov; bi = oi; }
        }
        if (lane == 0) {
            redf[warp] = ps; redf2[warp] = cpv; redf3[warp] = cmv;
            redf4[warp] = bv; redi[warp] = bi;
        }
        __syncthreads();
        if (warp == 0) {
            float a = redf[lane], c = redf2[lane], d = redf3[lane];
            float v = redf4[lane]; int i = redi[lane];
            for (int o = 16; o; o >>= 1) {
                a += __shfl_xor_sync(0xFFFFFFFFu, a, o);
                c += __shfl_xor_sync(0xFFFFFFFFu, c, o);
                d += __shfl_xor_sync(0xFFFFFFFFu, d, o);
                float ov = __shfl_xor_sync(0xFFFFFFFFu, v, o);
                int   oi = __shfl_xor_sync(0xFFFFFFFFu, i, o);
                if (ov > v || (ov == v && oi < i)) { v = ov; i = oi; }
            }
            if (lane == 0) {
                s_mean = a / (float)NS; s_cp = c; s_cm = d;
                s_maxm = v; s_anchor = i; s_pa = v * (1.0f / NC);
            }
        }
        __syncthreads();
    }
    // Fast path valid when max(m) > mean (always for non-constant m) AND
    // max(m) > 0 (so masked zeros can't exceed it). Else exact masked argmax.
    if (!(s_maxm > s_mean && s_maxm > 0.f)) {
        float bv = -1e30f; int bi = NS;
        if (act) { float v = (m > s_mean) ? m * (1.0f / NC) : 0.0f; bv = v; bi = tid; }
        for (int o = 16; o; o >>= 1) {
            float ov = __shfl_xor_sync(0xFFFFFFFFu, bv, o);
            int   oi = __shfl_xor_sync(0xFFFFFFFFu, bi, o);
            if (ov > bv || (ov == bv && oi < bi)) { bv = ov; bi = oi; }
        }
        if (lane == 0) { redf[warp] = bv; redi[warp] = bi; }
        __syncthreads();
        if (warp == 0) {
            float v = redf[lane]; int i = redi[lane];
            for (int o = 16; o; o >>= 1) {
                float ov = __shfl_xor_sync(0xFFFFFFFFu, v, o);
                int   oi = __shfl_xor_sync(0xFFFFFFFFu, i, o);
                if (ov > v || (ov == v && oi < i)) { v = ov; i = oi; }
            }
            if (lane == 0) { s_anchor = i; s_pa = msh[i] * (1.0f / NC); }
        }
        __syncthreads();
    }
    const int anchor = s_anchor;
    const float ai = (float)(anchor / NH), aj = (float)(anchor % NH);

    // ---- pass 2: w0 = sum pw*dist, w1 = sum pw*ang -----------------------
    {
        float w0 = 0.f, w1s = 0.f;
        if (act) {
            float p   = m * (1.0f / NC);
            float rc0 = ((float)(tid / NH) - ai) / (float)NH;
            float rc1 = ((float)(tid % NH) - aj) / (float)NH;
            w0  = p * sqrtf(rc0 * rc0 + rc1 * rc1);
            w1s = p * (atan2f(rc1, rc0) * 0.3183098861837907f + 1.0f) * 0.5f;
        }
        for (int o = 16; o; o >>= 1) {
            w0  += __shfl_xor_sync(0xFFFFFFFFu, w0,  o);
            w1s += __shfl_xor_sync(0xFFFFFFFFu, w1s, o);
        }
        if (lane == 0) { redf[warp] = w0; redf4[warp] = w1s; }
        __syncthreads();
        if (warp == 0) {
            float a = redf[lane], bb = redf4[lane];
            for (int o = 16; o; o >>= 1) {
                a  += __shfl_xor_sync(0xFFFFFFFFu, a,  o);
                bb += __shfl_xor_sync(0xFFFFFFFFu, bb, o);
            }
            if (lane == 0) { s_w0 = a; s_w1 = bb; }
        }
        __syncthreads();
    }

    // ---- coef[k] = (u>0 ? cp : cm) * u  (cp*u+ - cm*u- collapses) --------
    if (tid < KHID) {
        float u = s_w0 * w1[tid] + s_w1 * w1[KHID + tid];
        scoef[tid] = u * (u > 0.f ? s_cp : s_cm);
    }

    // ---- 3x3 conv + per-warp value histogram -----------------------------
    int vcc = 0; unsigned mm;
    if (act) {
        int i0 = tid / NH, j0 = tid % NH;
        #pragma unroll
        for (int di = -1; di <= 1; di++)
            #pragma unroll
            for (int dj = -1; dj <= 1; dj++) {
                int ii = i0 + di, jj = j0 + dj;
                if (ii >= 0 && ii < NH && jj >= 0 && jj < NH)
                    vcc += (2 - abs(di)) * (2 - abs(dj)) * (int)c0[ii * NH + jj];
            }
    }
    {
        int key = act ? vcc : 999;
        mm = __match_any_sync(0xFFFFFFFFu, key);
        if (act && lane == (__ffs(mm) - 1))
            whist[warp][vcc] = (unsigned char)__popc(mm);
    }
    __syncthreads();

    // ---- sfx[v] = # strictly greater (suffix over 256 bins) --------------
    int sh = 0, ss = 0;
    if (tid < 256) {
        #pragma unroll
        for (int r = 0; r < NWA; r++) sh += (int)whist[r][tid];
        ss = sh;
        #pragma unroll
        for (int o = 1; o < 32; o <<= 1) {
            int n = __shfl_up_sync(0xFFFFFFFFu, ss, o);
            if (lane >= o) ss += n;
        }
        if (lane == 31) redi[tid >> 5] = ss;
    }
    __syncthreads();
    if (tid < 256) {
        int off = 0, total = 0;
        #pragma unroll
        for (int r = 0; r < 8; r++) {
            int w = redi[r]; total += w; if (r < (tid >> 5)) off += w;
        }
        sfx[tid] = total - (ss + off);
    }
    __syncthreads();

    // ---- stable descending ranks -> smem patch list ----------------------
    if (act) {
        int g = sfx[vcc];
        if (g < seln) {
            int e = __popc(mm & ((1u << lane) - 1u));
            for (int r = 0; r < warp; r++) e += (int)whist[r][vcc];
            int rk = g + e;                 // ties by ascending index (stable)
            if (rk < seln) spatch[rk] = (short)(tid + 1);
        }
    }

    // ---- GEMV split by sub: 48 col-groups x 16 k-chunks of 32 ------------
    if (tid < 768) {
        const int g  = tid % 48;            // 4 cols/group: cols sub*192+4g..
        const int ks = tid / 48;            // 0..15
        const float4* w4 = (const float4*)w2 + sub * 48 + g;
        float4 acc = make_float4(0.f, 0.f, 0.f, 0.f);
        #pragma unroll 8
        for (int k = ks * 32; k < ks * 32 + 32; k++) {
            float c = scoef[k];
            float4 w = __ldg(w4 + (size_t)k * (ND / 4));
            acc.x += c * w.x; acc.y += c * w.y; acc.z += c * w.z; acc.w += c * w.w;
        }
        gp4[tid] = acc;
    }
    __syncthreads();
    if (tid < 48) {
        float4 v = make_float4(0.f, 0.f, 0.f, 0.f);
        #pragma unroll
        for (int r = 0; r < 16; r++) {
            float4 a = gp4[r * 48 + tid];
            v.x += a.x; v.y += a.y; v.z += a.z; v.w += a.w;
        }
        v.x *= s_pa; v.y *= s_pa; v.z *= s_pa; v.w *= s_pa;
        v.x = v.x > 0.f ? v.x : 0.2f * v.x;
        v.y = v.y > 0.f ? v.y : 0.2f * v.y;
        v.z = v.z > 0.f ? v.z : 0.2f * v.z;
        v.w = v.w > 0.f ? v.w : 0.2f * v.w;
        const int fi4 = b * NNtok * (ND / 4) + sub * 48 + tid;   // row 0
        float4 h4 = ((const float4*)hs)[fi4];
        v.x += h4.x; v.y += h4.y; v.z += h4.z; v.w += h4.w;
        ((float4*)out)[fi4] = v;
    }

    // ---- gather: rows q = sub, sub+4, ... (2-way unrolled) ---------------
    {
        const float4* hin = (const float4*)hs;
        float4* o4 = (float4*)out;
        const int nh = (seln - sub + 3) / 4;               // # rows we own
        const int tot = nh * (ND / 4);
        for (int t = tid; t < tot; t += 2 * TPB) {
            int t2 = t + TPB;
            int r0 = t / (ND / 4),  d0 = t - r0 * (ND / 4);
            int p0 = (int)spatch[4 * r0 + sub];
            float4 v0 = hin[(b * NNtok + p0) * (ND / 4) + d0];
            bool ok2 = (t2 < tot);
            float4 v1; int q1 = 0, d1 = 0;
            if (ok2) {
                int r1 = t2 / (ND / 4); d1 = t2 - r1 * (ND / 4);
                q1 = 4 * r1 + sub;
                int p1 = (int)spatch[q1];
                v1 = hin[(b * NNtok + p1) * (ND / 4) + d1];
            }
            o4[NB * NNtok * (ND / 4) + (b * seln + 4 * r0 + sub) * (ND / 4) + d0] = v0;
            if (ok2)
                o4[NB * NNtok * (ND / 4) + (b * seln + q1) * (ND / 4) + d1] = v1;
        }
    }
}

// ---------------- launch ----------------
extern "C" void kernel_launch(void* const* d_in, const int* in_sizes, int n_in,
                              void* d_out, int out_size)
{
    const float* hs = (const float*)d_in[0];
    const float* x  = (const float*)d_in[1];
    const float* w1 = (const float*)d_in[2];
    const float* w2 = (const float*)d_in[3];

    const int hs_elems = NB * NNtok * ND;
    int seln = (out_size - hs_elems) / (NB * ND);
    if (seln < 1) seln = 1;
    if (seln > NS) seln = NS;

    kAll<<<NCB + NCPB, TPB>>>(x, w1, w2, hs, (float*)d_out, seln);
}

// round 14
// speedup vs baseline: 1.6218x; 1.1228x over previous
#include <cuda_runtime.h>
#include <math.h>

#define NB 8
#define NC 12
#define NNtok 785
#define NS 784
#define NH 28
#define ND 768
#define KHID 512
#define PNUM 84
#define SCL 0.7f
#define TPB 1024
#define NWB 32
#define NWA 25                        // warps covering s<784
#define NSUB 8                        // compute sub-blocks per batch
#define NCB (NB * NSUB)               // 64 compute blocks
#define NC4TOT (NB * NS * (ND / 4))   // 1,204,224 float4 (rows 1..784)
#define NCPB (148 - NCB)              // 84 copy blocks -> grid 148 = 1 wave
#define CSTRIDE (NCPB * TPB)          // 86016; 14 * 86016 == NC4TOT exactly

__device__ __forceinline__ unsigned f2key(float v) {
    unsigned b = __float_as_uint(v);
    return (b & 0x80000000u) ? ~b : (b | 0x80000000u);   // order-preserving
}

__global__ __launch_bounds__(TPB) void kAll(
    const float* __restrict__ x,  const float* __restrict__ w1,
    const float* __restrict__ w2, const float* __restrict__ hs,
    float* __restrict__ out, int seln)
{
    const int tid = threadIdx.x, lane = tid & 31, warp = tid >> 5;

    if (blockIdx.x >= NCB) {
        // ========= copy blocks: hs rows 1..784 -> out (2 batches of 7) =====
        const float4* hin = (const float4*)hs;
        float4* o4 = (float4*)out;
        const int cb = blockIdx.x - NCB;
        #pragma unroll
        for (int half = 0; half < 2; half++) {
            float4 v[7]; int idx[7];
            #pragma unroll
            for (int j = 0; j < 7; j++) {
                int k = cb * TPB + tid + (half * 7 + j) * CSTRIDE;  // always < NC4TOT
                int b  = k / (NS * (ND / 4));
                int r  = k - b * (NS * (ND / 4));
                int n  = r / (ND / 4);
                int d4 = r - n * (ND / 4);
                idx[j] = (b * NNtok + n + 1) * (ND / 4) + d4;
                v[j]   = hin[idx[j]];
            }
            #pragma unroll
            for (int j = 0; j < 7; j++) o4[idx[j]] = v[j];
        }
        return;
    }

    // ============== compute block (b, sub): redundant per-batch stats ======
    __shared__ unsigned      msel[NC][25];      // selection bitmasks
    __shared__ int           hist[NC][256];     // per-channel radix hist
    __shared__ unsigned char whist[NWA][256];   // per-warp conv-value hist
    __shared__ unsigned char c0[NS];
    __shared__ float         msh[NS];
    __shared__ int           sfx[256];
    __shared__ short         spatch[NS];        // patch idx by rank
    __shared__ float         scoef[KHID];       // (u>0?cp:cm)*u
    __shared__ float4        gp4[32 * 24];      // GEMV k-chunk partials
    __shared__ float redf[NWB], redf2[NWB], redf3[NWB], redf4[NWB];
    __shared__ int   redi[NWB];
    __shared__ float s_mean, s_w0, s_w1, s_pa, s_cp, s_cm, s_maxm;
    __shared__ int   s_anchor;

    const int b = blockIdx.x >> 3, sub = blockIdx.x & 7;

    for (int i = tid; i < NWA * 256 / 4; i += TPB) ((int*)whist)[i] = 0;

    // ---- warp-local top-84: 2 radix passes (16 bits) + exact cleanup -----
    if (warp < NC) {
        const int c = warp;
        const float* row = x + ((long long)(b * NC + c)) * NNtok * NNtok + 1;
        unsigned ukey[25];
        #pragma unroll
        for (int j = 0; j < 25; j++) {
            int s = lane + 32 * j;
            ukey[j] = (s < NS) ? f2key(row[s]) : 0u;   // 0 = smallest key
        }
        unsigned pref = 0u; int rem = PNUM;
        #pragma unroll
        for (int pass = 0; pass < 2; pass++) {
            const int shift = 24 - 8 * pass;
            const unsigned mhi = (pass == 0) ? 0u : 0xFF000000u;
            #pragma unroll
            for (int i = 0; i < 8; i++) hist[c][lane * 8 + i] = 0;
            __syncwarp();
            #pragma unroll
            for (int j = 0; j < 25; j++) {
                unsigned u = ukey[j];
                if ((lane + 32 * j < NS) && (u & mhi) == pref)
                    atomicAdd(&hist[c][(u >> shift) & 255u], 1);
            }
            __syncwarp();
            int hh[8], S = 0;
            #pragma unroll
            for (int i = 0; i < 8; i++) { hh[i] = hist[c][lane * 8 + i]; S += hh[i]; }
            int s = S;                                 // suffix over lanes
            #pragma unroll
            for (int o = 1; o < 32; o <<= 1) {
                int n = __shfl_down_sync(0xFFFFFFFFu, s, o);
                if (lane + o < 32) s += n;
            }
            int run = s - S;                           // sum over lanes > me
            int fbin = -1, fgt = 0;
            #pragma unroll
            for (int i = 7; i >= 0; i--) {
                int gt = run;                          // # keys strictly greater
                if (gt < rem && gt + hh[i] >= rem) { fbin = lane * 8 + i; fgt = gt; }
                run += hh[i];
            }
            unsigned fm = __ballot_sync(0xFFFFFFFFu, fbin >= 0);
            int src = __ffs(fm) - 1;
            int bin = __shfl_sync(0xFFFFFFFFu, fbin, src);
            int gt  = __shfl_sync(0xFFFFFFFFu, fgt, src);
            pref |= ((unsigned)bin) << shift;
            rem  -= gt;
            __syncwarp();
        }
        // cleanup: exact rem-th largest among keys with 16-bit prefix `pref`
        const unsigned p16 = pref >> 16;
        unsigned bound = 0xFFFFFFFFu;   // inclusive upper bound on candidates
        unsigned T = 0u; int need = rem, cntT = 0;
        while (true) {
            unsigned mymax = 0u;
            #pragma unroll
            for (int j = 0; j < 25; j++) {
                unsigned u = ukey[j];
                if ((lane + 32 * j < NS) && (u >> 16) == p16 && u <= bound)
                    mymax = mymax > u ? mymax : u;
            }
            #pragma unroll
            for (int o = 16; o; o >>= 1) {
                unsigned ov = __shfl_xor_sync(0xFFFFFFFFu, mymax, o);
                mymax = mymax > ov ? mymax : ov;
            }
            int cnt = 0;
            #pragma unroll
            for (int j = 0; j < 25; j++)
                cnt += ((lane + 32 * j < NS) && ukey[j] == mymax) ? 1 : 0;
            #pragma unroll
            for (int o = 16; o; o >>= 1)
                cnt += __shfl_xor_sync(0xFFFFFFFFu, cnt, o);
            if (cnt >= need) { T = mymax; cntT = cnt; break; }
            need -= cnt; bound = mymax - 1u;
        }
        if (cntT == need) {
            // fast path (virtually always): take all T-ties
            #pragma unroll
            for (int j = 0; j < 25; j++) {
                bool sel = (lane + 32 * j < NS) && (ukey[j] >= T);
                unsigned smask = __ballot_sync(0xFFFFFFFFu, sel);
                if (lane == 0) msel[c][j] = smask;
            }
        } else {
            int cum = 0;
            #pragma unroll
            for (int j = 0; j < 25; j++) {
                bool valid = (lane + 32 * j < NS);
                unsigned u = valid ? ukey[j] : (T ^ 1u);
                unsigned eqm = __ballot_sync(0xFFFFFFFFu, valid && (u == T));
                bool sel = valid && (u > T ||
                          (u == T && (cum + __popc(eqm & ((1u << lane) - 1u)) < need)));
                unsigned smask = __ballot_sync(0xFFFFFFFFu, sel);
                if (lane == 0) msel[c][j] = smask;
                cum += __popc(eqm);
            }
        }
    }
    __syncthreads();

    // ---- m[s] = sum_c (sel ? v : 0.7v);  c0[s] = sum_c sel ---------------
    const bool act = (tid < NS);
    float m = 0.f;
    if (act) {
        const long long xb = (long long)b * NC * NNtok * NNtok;
        const int jw = tid >> 5; const unsigned bit = 1u << (tid & 31);
        int cnt = 0;
        #pragma unroll
        for (int c = 0; c < NC; c++) {
            float v = x[xb + (long long)c * NNtok * NNtok + 1 + tid];  // L1-hot
            bool sel = (msel[c][jw] & bit) != 0u;
            m += sel ? v : v * SCL;
            cnt += sel ? 1 : 0;
        }
        msh[tid] = m;
        c0[tid]  = (unsigned char)cnt;
    }

    // ---- pass 1: mean + c+ + c- + (max m, argmax) simultaneously ---------
    {
        float p  = act ? m * (1.0f / NC) : 0.f;
        float ps = act ? m : 0.f;
        float cpv = (p > 0.f) ? p * p : 0.f;
        float cmv = (p < 0.f) ? p * p : 0.f;
        float bv = act ? m : -1e30f; int bi = act ? tid : NS;
        for (int o = 16; o; o >>= 1) {
            ps  += __shfl_xor_sync(0xFFFFFFFFu, ps,  o);
            cpv += __shfl_xor_sync(0xFFFFFFFFu, cpv, o);
            cmv += __shfl_xor_sync(0xFFFFFFFFu, cmv, o);
            float ov = __shfl_xor_sync(0xFFFFFFFFu, bv, o);
            int   oi = __shfl_xor_sync(0xFFFFFFFFu, bi, o);
            if (ov > bv || (ov == bv && oi < bi)) { bv = ov; bi = oi; }
        }
        if (lane == 0) {
            redf[warp] = ps; redf2[warp] = cpv; redf3[warp] = cmv;
            redf4[warp] = bv; redi[warp] = bi;
        }
        __syncthreads();
        if (warp == 0) {
            float a = redf[lane], c = redf2[lane], d = redf3[lane];
            float v = redf4[lane]; int i = redi[lane];
            for (int o = 16; o; o >>= 1) {
                a += __shfl_xor_sync(0xFFFFFFFFu, a, o);
                c += __shfl_xor_sync(0xFFFFFFFFu, c, o);
                d += __shfl_xor_sync(0xFFFFFFFFu, d, o);
                float ov = __shfl_xor_sync(0xFFFFFFFFu, v, o);
                int   oi = __shfl_xor_sync(0xFFFFFFFFu, i, o);
                if (ov > v || (ov == v && oi < i)) { v = ov; i = oi; }
            }
            if (lane == 0) {
                s_mean = a / (float)NS; s_cp = c; s_cm = d;
                s_maxm = v; s_anchor = i; s_pa = v * (1.0f / NC);
            }
        }
        __syncthreads();
    }
    // Fast path valid when max(m) > mean AND max(m) > 0; else exact masked argmax.
    if (!(s_maxm > s_mean && s_maxm > 0.f)) {
        float bv = -1e30f; int bi = NS;
        if (act) { float v = (m > s_mean) ? m * (1.0f / NC) : 0.0f; bv = v; bi = tid; }
        for (int o = 16; o; o >>= 1) {
            float ov = __shfl_xor_sync(0xFFFFFFFFu, bv, o);
            int   oi = __shfl_xor_sync(0xFFFFFFFFu, bi, o);
            if (ov > bv || (ov == bv && oi < bi)) { bv = ov; bi = oi; }
        }
        if (lane == 0) { redf[warp] = bv; redi[warp] = bi; }
        __syncthreads();
        if (warp == 0) {
            float v = redf[lane]; int i = redi[lane];
            for (int o = 16; o; o >>= 1) {
                float ov = __shfl_xor_sync(0xFFFFFFFFu, v, o);
                int   oi = __shfl_xor_sync(0xFFFFFFFFu, i, o);
                if (ov > v || (ov == v && oi < i)) { v = ov; i = oi; }
            }
            if (lane == 0) { s_anchor = i; s_pa = msh[i] * (1.0f / NC); }
        }
        __syncthreads();
    }
    const int anchor = s_anchor;
    const float ai = (float)(anchor / NH), aj = (float)(anchor % NH);

    // ---- pass 2: w0 = sum pw*dist, w1 = sum pw*ang -----------------------
    {
        float w0 = 0.f, w1s = 0.f;
        if (act) {
            float p   = m * (1.0f / NC);
            float rc0 = ((float)(tid / NH) - ai) / (float)NH;
            float rc1 = ((float)(tid % NH) - aj) / (float)NH;
            w0  = p * sqrtf(rc0 * rc0 + rc1 * rc1);
            w1s = p * (atan2f(rc1, rc0) * 0.3183098861837907f + 1.0f) * 0.5f;
        }
        for (int o = 16; o; o >>= 1) {
            w0  += __shfl_xor_sync(0xFFFFFFFFu, w0,  o);
            w1s += __shfl_xor_sync(0xFFFFFFFFu, w1s, o);
        }
        if (lane == 0) { redf[warp] = w0; redf4[warp] = w1s; }
        __syncthreads();
        if (warp == 0) {
            float a = redf[lane], bb = redf4[lane];
            for (int o = 16; o; o >>= 1) {
                a  += __shfl_xor_sync(0xFFFFFFFFu, a,  o);
                bb += __shfl_xor_sync(0xFFFFFFFFu, bb, o);
            }
            if (lane == 0) { s_w0 = a; s_w1 = bb; }
        }
        __syncthreads();
    }

    // ---- coef[k] = (u>0 ? cp : cm) * u  (cp*u+ - cm*u- collapses) --------
    if (tid < KHID) {
        float u = s_w0 * w1[tid] + s_w1 * w1[KHID + tid];
        scoef[tid] = u * (u > 0.f ? s_cp : s_cm);
    }

    // ---- 3x3 conv + per-warp value histogram -----------------------------
    int vcc = 0; unsigned mm;
    if (act) {
        int i0 = tid / NH, j0 = tid % NH;
        #pragma unroll
        for (int di = -1; di <= 1; di++)
            #pragma unroll
            for (int dj = -1; dj <= 1; dj++) {
                int ii = i0 + di, jj = j0 + dj;
                if (ii >= 0 && ii < NH && jj >= 0 && jj < NH)
                    vcc += (2 - abs(di)) * (2 - abs(dj)) * (int)c0[ii * NH + jj];
            }
    }
    {
        int key = act ? vcc : 999;
        mm = __match_any_sync(0xFFFFFFFFu, key);
        if (act && lane == (__ffs(mm) - 1))
            whist[warp][vcc] = (unsigned char)__popc(mm);
    }
    __syncthreads();

    // ---- sfx[v] = # strictly greater (suffix over 256 bins) --------------
    int sh = 0, ss = 0;
    if (tid < 256) {
        #pragma unroll
        for (int r = 0; r < NWA; r++) sh += (int)whist[r][tid];
        ss = sh;
        #pragma unroll
        for (int o = 1; o < 32; o <<= 1) {
            int n = __shfl_up_sync(0xFFFFFFFFu, ss, o);
            if (lane >= o) ss += n;
        }
        if (lane == 31) redi[tid >> 5] = ss;
    }
    __syncthreads();
    if (tid < 256) {
        int off = 0, total = 0;
        #pragma unroll
        for (int r = 0; r < 8; r++) {
            int w = redi[r]; total += w; if (r < (tid >> 5)) off += w;
        }
        sfx[tid] = total - (ss + off);
    }
    __syncthreads();

    // ---- stable descending ranks -> smem patch list ----------------------
    if (act) {
        int g = sfx[vcc];
        if (g < seln) {
            int e = __popc(mm & ((1u << lane) - 1u));
            for (int r = 0; r < warp; r++) e += (int)whist[r][vcc];
            int rk = g + e;                 // ties by ascending index (stable)
            if (rk < seln) spatch[rk] = (short)(tid + 1);
        }
    }

    // ---- GEMV split by sub: 24 col-groups x 32 k-chunks of 16 ------------
    if (tid < 768) {
        const int g  = tid % 24;            // 4 cols/group: cols sub*96+4g..
        const int ks = tid / 24;            // 0..31
        const float4* w4 = (const float4*)w2 + sub * 24 + g;
        float4 acc = make_float4(0.f, 0.f, 0.f, 0.f);
        #pragma unroll 8
        for (int k = ks * 16; k < ks * 16 + 16; k++) {
            float c = scoef[k];
            float4 w = __ldg(w4 + (size_t)k * (ND / 4));
            acc.x += c * w.x; acc.y += c * w.y; acc.z += c * w.z; acc.w += c * w.w;
        }
        gp4[tid] = acc;
    }
    __syncthreads();
    if (tid < 24) {
        float4 v = make_float4(0.f, 0.f, 0.f, 0.f);
        #pragma unroll
        for (int r = 0; r < 32; r++) {
            float4 a = gp4[r * 24 + tid];
            v.x += a.x; v.y += a.y; v.z += a.z; v.w += a.w;
        }
        v.x *= s_pa; v.y *= s_pa; v.z *= s_pa; v.w *= s_pa;
        v.x = v.x > 0.f ? v.x : 0.2f * v.x;
        v.y = v.y > 0.f ? v.y : 0.2f * v.y;
        v.z = v.z > 0.f ? v.z : 0.2f * v.z;
        v.w = v.w > 0.f ? v.w : 0.2f * v.w;
        const int fi4 = b * NNtok * (ND / 4) + sub * 24 + tid;   // row 0
        float4 h4 = ((const float4*)hs)[fi4];
        v.x += h4.x; v.y += h4.y; v.z += h4.z; v.w += h4.w;
        ((float4*)out)[fi4] = v;
    }

    // ---- gather: rows q = sub, sub+8, ... --------------------------------
    {
        const float4* hin = (const float4*)hs;
        float4* o4 = (float4*)out;
        const int nh = (seln - sub + 7) / 8;               // # rows we own
        const int tot = nh * (ND / 4);
        for (int t = tid; t < tot; t += TPB) {
            int r  = t / (ND / 4);
            int d4 = t - r * (ND / 4);
            int q  = 8 * r + sub;
            int p  = (int)spatch[q];       // in [1,784]: unmodified hs rows
            o4[NB * NNtok * (ND / 4) + (b * seln + q) * (ND / 4) + d4] =
                hin[(b * NNtok + p) * (ND / 4) + d4];
        }
    }
}

// ---------------- launch ----------------
extern "C" void kernel_launch(void* const* d_in, const int* in_sizes, int n_in,
                              void* d_out, int out_size)
{
    const float* hs = (const float*)d_in[0];
    const float* x  = (const float*)d_in[1];
    const float* w1 = (const float*)d_in[2];
    const float* w2 = (const float*)d_in[3];

    const int hs_elems = NB * NNtok * ND;
    int seln = (out_size - hs_elems) / (NB * ND);
    if (seln < 1) seln = 1;
    if (seln > NS) seln = NS;

    kAll<<<NCB + NCPB, TPB>>>(x, w1, w2, hs, (float*)d_out, seln);
}